// round 5
// baseline (speedup 1.0000x reference)
#include <cuda_runtime.h>
#include <math.h>
#include <stdint.h>

#define NR 8192
#define D  512
#define SCALEF 0.1f

__device__ float g_E[(size_t)NR * NR];      // 256 MB: E = exp(sim-1), k-permuted columns
__device__ float g_xn[(size_t)NR * D];      // normalized x, k-permuted features
__device__ float g_xt[(size_t)D * NR];      // x^T [512][8192], k-permuted columns
__device__ float g_xneg[(size_t)NR * D];
__device__ float g_invr[NR];                // natural order
__device__ float g_invr_p[NR];              // k-permuted order

// stored position p (within 8-group) holds logical element l(p) = (p>>1) + 4*(p&1)
__device__ __host__ __forceinline__ int lperm(int p) { return (p >> 1) + 4 * (p & 1); }
__device__ __forceinline__ int pm(int p) { return (p & ~7) | lperm(p & 7); }

#define ROWW 40                 // smem row stride in words (conflict-free for LDS.64 frags)
#define TILEW (128 * ROWW)      // 5120 words per operand tile
#define STAGEW (2 * TILEW)
#define SMEM_BYTES (2 * STAGEW * 4)  // 81920

__device__ __forceinline__ float warpReduceSum(float v) {
#pragma unroll
    for (int o = 16; o > 0; o >>= 1) v += __shfl_xor_sync(0xffffffffu, v, o);
    return v;
}
__device__ __forceinline__ uint32_t smem_u32(const void* p) {
    uint32_t a;
    asm("{ .reg .u64 t; cvta.to.shared.u64 t, %1; cvt.u32.u64 %0, t; }" : "=r"(a) : "l"(p));
    return a;
}
__device__ __forceinline__ void cp16(uint32_t s, const void* g) {
    asm volatile("cp.async.cg.shared.global [%0], [%1], 16;" :: "r"(s), "l"(g));
}
#define CP_COMMIT() asm volatile("cp.async.commit_group;")
#define CP_WAIT1()  asm volatile("cp.async.wait_group 1;")
#define CP_WAIT0()  asm volatile("cp.async.wait_group 0;")

__device__ __forceinline__ void mma_tf32(float* c, uint32_t a0, uint32_t a1, uint32_t a2,
                                         uint32_t a3, uint32_t b0, uint32_t b1) {
    asm volatile(
        "mma.sync.aligned.m16n8k8.row.col.f32.tf32.tf32.f32 "
        "{%0,%1,%2,%3}, {%4,%5,%6,%7}, {%8,%9}, {%0,%1,%2,%3};"
        : "+f"(c[0]), "+f"(c[1]), "+f"(c[2]), "+f"(c[3])
        : "r"(a0), "r"(a1), "r"(a2), "r"(a3), "r"(b0), "r"(b1));
}

// ---------------- prep: L2-normalize rows, write k-permuted ----------------
__global__ void prep_kernel(const float* __restrict__ x) {
    __shared__ float sred[4];
    int row = blockIdx.x;
    int t = threadIdx.x;  // 128 threads
    float4 a = ((const float4*)(x + (size_t)row * D))[t];
    float ss = a.x * a.x + a.y * a.y + a.z * a.z + a.w * a.w;
    ss = warpReduceSum(ss);
    if ((t & 31) == 0) sred[t >> 5] = ss;
    __syncthreads();
    float tot = sred[0] + sred[1] + sred[2] + sred[3];
    float inv = 1.0f / fmaxf(sqrtf(tot), 1e-12f);
    float v[4] = {a.x * inv, a.y * inv, a.z * inv, a.w * inv};
    float* dst = g_xn + (size_t)row * D;
#pragma unroll
    for (int e = 0; e < 4; e++) {
        int f = 4 * t + e;
        int p = (f & ~7) | (((f & 3) << 1) | ((f >> 2) & 1));
        dst[p] = v[e];
    }
}

// ---------------- transpose x -> g_xt [512][8192], k-permuted columns ----------------
__global__ void transpose_kernel(const float* __restrict__ x) {
    __shared__ float tl[32][33];
    int k0 = blockIdx.x * 32, n0 = blockIdx.y * 32;
    int tx = threadIdx.x, ty = threadIdx.y;  // 32 x 8
#pragma unroll
    for (int r = 0; r < 32; r += 8)
        tl[ty + r][tx] = x[(size_t)(k0 + ty + r) * D + n0 + tx];
    __syncthreads();
    int ltx = (tx & ~7) | lperm(tx & 7);
#pragma unroll
    for (int r = 0; r < 32; r += 8)
        g_xt[(size_t)(n0 + ty + r) * NR + k0 + tx] = tl[ltx][ty + r];
}

// ============== GEMM1: E = exp(xn @ xn^T - 1), triangular grid + mirror ==============
__global__ void __launch_bounds__(128) gemm1_kernel() {
    int kid = blockIdx.x;
    int bj = (int)((sqrtf(8.0f * (float)kid + 1.0f) - 1.0f) * 0.5f);
    while ((bj + 1) * (bj + 2) / 2 <= kid) bj++;
    while (bj * (bj + 1) / 2 > kid) bj--;
    int bi = kid - bj * (bj + 1) / 2;
    const int I0 = bi * 128, J0 = bj * 128;

    extern __shared__ uint32_t su[];
    uint32_t sbase = smem_u32(su);
    int t = threadIdx.x, wid = t >> 5, lane = t & 31;
    int g = lane >> 2, tq = lane & 3;
    int warpM = (wid >> 1) * 64, warpN = (wid & 1) * 64;

    const float* aG = g_xn + (size_t)(I0 + t) * D;
    const float* bG = g_xn + (size_t)(J0 + t) * D;
    uint32_t dstA = sbase + (uint32_t)(t * ROWW) * 4;
    uint32_t dstB = dstA + TILEW * 4;

    auto copy_stage = [&](int stage, int k0) {
        uint32_t off = (uint32_t)(stage * STAGEW) * 4;
#pragma unroll
        for (int q = 0; q < 8; q++) {
            cp16(dstA + off + q * 16, aG + k0 + q * 4);
            cp16(dstB + off + q * 16, bG + k0 + q * 4);
        }
        CP_COMMIT();
    };

    float acc[4][8][4];
#pragma unroll
    for (int i = 0; i < 4; i++)
#pragma unroll
        for (int j = 0; j < 8; j++)
#pragma unroll
            for (int q = 0; q < 4; q++) acc[i][j][q] = 0.f;

    const int C = D / 32;  // 16
    copy_stage(0, 0);
    copy_stage(1, 32);
    CP_WAIT1();
    __syncthreads();

    for (int c = 0; c < C; c++) {
        const uint32_t* sA = su + (c & 1) * STAGEW;
        const uint32_t* sB = sA + TILEW;
#pragma unroll
        for (int s = 0; s < 4; s++) {
            uint32_t af[4][4], bf[8][2];
#pragma unroll
            for (int i = 0; i < 4; i++) {
                const uint32_t* pa = sA + (warpM + i * 16 + g) * ROWW + 8 * s + 2 * tq;
                uint2 lo = *(const uint2*)pa;
                uint2 hi = *(const uint2*)(pa + 8 * ROWW);
                af[i][0] = lo.x; af[i][1] = hi.x; af[i][2] = lo.y; af[i][3] = hi.y;
            }
#pragma unroll
            for (int j = 0; j < 8; j++) {
                uint2 b = *(const uint2*)(sB + (warpN + j * 8 + g) * ROWW + 8 * s + 2 * tq);
                bf[j][0] = b.x; bf[j][1] = b.y;
            }
#pragma unroll
            for (int i = 0; i < 4; i++)
#pragma unroll
                for (int j = 0; j < 8; j++)
                    mma_tf32(acc[i][j], af[i][0], af[i][1], af[i][2], af[i][3],
                             bf[j][0], bf[j][1]);
        }
        __syncthreads();
        if (c + 2 < C) { copy_stage(c & 1, (c + 2) * 32); CP_WAIT1(); }
        else CP_WAIT0();
        __syncthreads();
    }

    // epilogue: exp(s-1) -> smem[128][129] (logical cols) -> coalesced permuted writes
    float* eb = (float*)su;
#pragma unroll
    for (int i = 0; i < 4; i++)
#pragma unroll
        for (int j = 0; j < 8; j++) {
            int r0 = warpM + i * 16 + g;
            int c0 = warpN + j * 8 + 2 * tq;
            eb[r0 * 129 + c0]           = __expf(acc[i][j][0] - 1.0f);
            eb[r0 * 129 + c0 + 1]       = __expf(acc[i][j][1] - 1.0f);
            eb[(r0 + 8) * 129 + c0]     = __expf(acc[i][j][2] - 1.0f);
            eb[(r0 + 8) * 129 + c0 + 1] = __expf(acc[i][j][3] - 1.0f);
        }
    __syncthreads();

    // each warp: 32 rows; lanes cover one full row per iteration (coalesced 512B)
#pragma unroll 1
    for (int it = 0; it < 32; it++) {
        int row = wid * 32 + it;
        int p0 = lane * 4;
        const float* src = eb + row * 129;
        float4 v;
        v.x = src[pm(p0)]; v.y = src[pm(p0 + 1)];
        v.z = src[pm(p0 + 2)]; v.w = src[pm(p0 + 3)];
        *(float4*)(g_E + (size_t)(I0 + row) * NR + J0 + p0) = v;
        float4 w;
        w.x = eb[pm(p0) * 129 + row];     w.y = eb[pm(p0 + 1) * 129 + row];
        w.z = eb[pm(p0 + 2) * 129 + row]; w.w = eb[pm(p0 + 3) * 129 + row];
        *(float4*)(g_E + (size_t)(J0 + row) * NR + I0 + p0) = w;
    }
}

// ---------------- row sums of E -> invr ----------------
__global__ void rowsum_kernel() {
    __shared__ float sred[8];
    int row = blockIdx.x, t = threadIdx.x;  // 256 threads
    const float4* e = (const float4*)(g_E + (size_t)row * NR);
    float s = 0.f;
#pragma unroll
    for (int i = 0; i < 8; i++) {
        float4 v = e[t + 256 * i];
        s += (v.x + v.y) + (v.z + v.w);
    }
    s = warpReduceSum(s);
    if ((t & 31) == 0) sred[t >> 5] = s;
    __syncthreads();
    if (t == 0) {
        float tot = 0.f;
#pragma unroll
        for (int i = 0; i < 8; i++) tot += sred[i];
        g_invr[row] = 1.0f / tot;
    }
}

__global__ void permute_invr_kernel() {
    int i = blockIdx.x * 256 + threadIdx.x;
    g_invr_p[i] = g_invr[pm(i)];
}

// ============== GEMM2: xneg = [E*(invr_i+invr_k)] @ x ==============
__global__ void __launch_bounds__(128) gemm2_kernel() {
    const int n0 = blockIdx.x * 128;  // 0..3
    const int I0 = blockIdx.y * 128;  // 0..63

    extern __shared__ uint32_t su[];
    uint32_t sbase = smem_u32(su);
    int t = threadIdx.x, wid = t >> 5, lane = t & 31;
    int g = lane >> 2, tq = lane & 3;
    int warpM = (wid >> 1) * 64, warpN = (wid & 1) * 64;

    const float ri = g_invr[I0 + t];
    const float* aG = g_E + (size_t)(I0 + t) * NR;   // k-permuted stored order
    const float* bG = g_xt + (size_t)(n0 + t) * NR;  // k-permuted stored order
    uint32_t stsA = sbase + (uint32_t)(t * ROWW) * 4;
    uint32_t dstB = stsA + TILEW * 4;

    float4 pa[8];
    auto ldgA = [&](int k0) {
#pragma unroll
        for (int q = 0; q < 8; q++) pa[q] = ((const float4*)(aG + k0))[q];
    };
    auto stsA_f = [&](int stage, int k0) {
        const float4* rk = (const float4*)(g_invr_p + k0);
        uint32_t dst = stsA + (uint32_t)(stage * STAGEW) * 4;
#pragma unroll
        for (int q = 0; q < 8; q++) {
            float4 rv = __ldg(&rk[q]);
            float4 v = make_float4(pa[q].x * (ri + rv.x), pa[q].y * (ri + rv.y),
                                   pa[q].z * (ri + rv.z), pa[q].w * (ri + rv.w));
            asm volatile("st.shared.v4.b32 [%0], {%1,%2,%3,%4};"
                         :: "r"(dst + q * 16), "f"(v.x), "f"(v.y), "f"(v.z), "f"(v.w));
        }
    };
    auto cpB = [&](int stage, int k0) {
        uint32_t off = (uint32_t)(stage * STAGEW) * 4;
#pragma unroll
        for (int q = 0; q < 8; q++)
            cp16(dstB + off + q * 16, bG + k0 + q * 4);
        CP_COMMIT();
    };

    float acc[4][8][4];
#pragma unroll
    for (int i = 0; i < 4; i++)
#pragma unroll
        for (int j = 0; j < 8; j++)
#pragma unroll
            for (int q = 0; q < 4; q++) acc[i][j][q] = 0.f;

    const int C = NR / 32;  // 256
    ldgA(0); stsA_f(0, 0); cpB(0, 0);
    ldgA(32);
    cpB(1, 32);
    CP_WAIT1();
    __syncthreads();

    for (int c = 0; c < C; c++) {
        if (c + 1 < C) stsA_f((c + 1) & 1, (c + 1) * 32);
        if (c + 2 < C) ldgA((c + 2) * 32);
        const uint32_t* sA = su + (c & 1) * STAGEW;
        const uint32_t* sB = sA + TILEW;
#pragma unroll
        for (int s = 0; s < 4; s++) {
            uint32_t af[4][4], bf[8][2];
#pragma unroll
            for (int i = 0; i < 4; i++) {
                const uint32_t* p = sA + (warpM + i * 16 + g) * ROWW + 8 * s + 2 * tq;
                uint2 lo = *(const uint2*)p;
                uint2 hi = *(const uint2*)(p + 8 * ROWW);
                af[i][0] = lo.x; af[i][1] = hi.x; af[i][2] = lo.y; af[i][3] = hi.y;
            }
#pragma unroll
            for (int j = 0; j < 8; j++) {
                uint2 b = *(const uint2*)(sB + (warpN + j * 8 + g) * ROWW + 8 * s + 2 * tq);
                bf[j][0] = b.x; bf[j][1] = b.y;
            }
#pragma unroll
            for (int i = 0; i < 4; i++)
#pragma unroll
                for (int j = 0; j < 8; j++)
                    mma_tf32(acc[i][j], af[i][0], af[i][1], af[i][2], af[i][3],
                             bf[j][0], bf[j][1]);
        }
        __syncthreads();
        if (c + 2 < C) { cpB(c & 1, (c + 2) * 32); CP_WAIT1(); }
        else CP_WAIT0();
        __syncthreads();
    }

    // epilogue: direct float2 stores (n not permuted)
#pragma unroll
    for (int i = 0; i < 4; i++)
#pragma unroll
        for (int j = 0; j < 8; j++) {
            int r0 = I0 + warpM + i * 16 + g;
            int c0 = n0 + warpN + j * 8 + 2 * tq;
            *(float2*)(g_xneg + (size_t)r0 * D + c0)       = make_float2(acc[i][j][0], acc[i][j][1]);
            *(float2*)(g_xneg + (size_t)(r0 + 8) * D + c0) = make_float2(acc[i][j][2], acc[i][j][3]);
        }
}

// ---------------- y = x - SCALE*xneg, LayerNorm ----------------
__global__ void ln_kernel(const float* __restrict__ x, const float* __restrict__ gamma,
                          const float* __restrict__ beta, float* __restrict__ out) {
    __shared__ float s1[4], s2[4];
    int row = blockIdx.x, t = threadIdx.x;  // 128 threads
    float4 xv = ((const float4*)(x + (size_t)row * D))[t];
    float4 nv = ((const float4*)(g_xneg + (size_t)row * D))[t];
    float4 y = make_float4(xv.x - SCALEF * nv.x, xv.y - SCALEF * nv.y,
                           xv.z - SCALEF * nv.z, xv.w - SCALEF * nv.w);
    float s = y.x + y.y + y.z + y.w;
    float q = y.x * y.x + y.y * y.y + y.z * y.z + y.w * y.w;
    s = warpReduceSum(s);
    q = warpReduceSum(q);
    if ((t & 31) == 0) { s1[t >> 5] = s; s2[t >> 5] = q; }
    __syncthreads();
    float sum = s1[0] + s1[1] + s1[2] + s1[3];
    float sq  = s2[0] + s2[1] + s2[2] + s2[3];
    float mean = sum * (1.0f / D);
    float var = sq * (1.0f / D) - mean * mean;
    float rstd = rsqrtf(var + 1e-6f);
    float4 gm = ((const float4*)gamma)[t];
    float4 b = ((const float4*)beta)[t];
    float4 o;
    o.x = (y.x - mean) * rstd * gm.x + b.x;
    o.y = (y.y - mean) * rstd * gm.y + b.y;
    o.z = (y.z - mean) * rstd * gm.z + b.z;
    o.w = (y.w - mean) * rstd * gm.w + b.w;
    ((float4*)out)[(size_t)row * (D / 4) + t] = o;
}

extern "C" void kernel_launch(void* const* d_in, const int* in_sizes, int n_in,
                              void* d_out, int out_size) {
    const float* x     = (const float*)d_in[0];
    const float* gamma = (const float*)d_in[1];
    const float* beta  = (const float*)d_in[2];
    float* out = (float*)d_out;

    cudaFuncSetAttribute(gemm1_kernel, cudaFuncAttributeMaxDynamicSharedMemorySize, SMEM_BYTES);
    cudaFuncSetAttribute(gemm2_kernel, cudaFuncAttributeMaxDynamicSharedMemorySize, SMEM_BYTES);

    prep_kernel<<<NR, 128>>>(x);
    transpose_kernel<<<dim3(NR / 32, D / 32), dim3(32, 8)>>>(x);
    gemm1_kernel<<<64 * 65 / 2, 128, SMEM_BYTES>>>();
    rowsum_kernel<<<NR, 256>>>();
    permute_invr_kernel<<<NR / 256, 256>>>();
    gemm2_kernel<<<dim3(4, 64), 128, SMEM_BYTES>>>();
    ln_kernel<<<NR, 128>>>(x, gamma, beta, out);
}

// round 6
// speedup vs baseline: 2.1851x; 2.1851x over previous
#include <cuda_runtime.h>
#include <cuda_fp16.h>
#include <math.h>
#include <stdint.h>

#define NR 8192
#define D  512
#define SCALEF 0.1f

__device__ __half g_Eh[(size_t)NR * NR];     // 128 MB: E fp16, k-word-permuted columns
__device__ __half g_xnh[(size_t)NR * D];     // normalized x fp16, permuted features
__device__ __half g_xth[(size_t)D * NR];     // x^T fp16 [512][8192], permuted columns
__device__ float  g_xneg[(size_t)NR * D];
__device__ float  g_invr[NR];                // natural order
__device__ float  g_invr_p[NR];              // stored(half)-position order

// word-level perm within 8-word (16-half) groups: stored word p holds logical word
// l(p) = (p>>1) + 4*(p&1); inverse: logical w stored at 2*(w&3) + (w>>2)
__device__ __host__ __forceinline__ int lword(int p) { return (p >> 1) + 4 * (p & 1); }

#define ROWW 40                   // smem row stride in 32-bit words (rows hold 32 data words)
#define A_TILE_W (128 * ROWW)     // 5120
#define B_TILE_W (256 * ROWW)     // 10240
#define STAGE_W  (A_TILE_W + B_TILE_W)
#define SMEM_BYTES (2 * STAGE_W * 4)   // 122880

__device__ __forceinline__ float warpReduceSum(float v) {
#pragma unroll
    for (int o = 16; o > 0; o >>= 1) v += __shfl_xor_sync(0xffffffffu, v, o);
    return v;
}
__device__ __forceinline__ uint32_t smem_u32(const void* p) {
    uint32_t a;
    asm("{ .reg .u64 t; cvta.to.shared.u64 t, %1; cvt.u32.u64 %0, t; }" : "=r"(a) : "l"(p));
    return a;
}
__device__ __forceinline__ void cp16(uint32_t s, const void* g) {
    asm volatile("cp.async.cg.shared.global [%0], [%1], 16;" :: "r"(s), "l"(g));
}
#define CP_COMMIT() asm volatile("cp.async.commit_group;")
#define CP_WAIT1()  asm volatile("cp.async.wait_group 1;")
#define CP_WAIT0()  asm volatile("cp.async.wait_group 0;")

__device__ __forceinline__ void mma_f16(float* c, uint32_t a0, uint32_t a1, uint32_t a2,
                                        uint32_t a3, uint32_t b0, uint32_t b1) {
    asm volatile(
        "mma.sync.aligned.m16n8k16.row.col.f32.f16.f16.f32 "
        "{%0,%1,%2,%3}, {%4,%5,%6,%7}, {%8,%9}, {%0,%1,%2,%3};"
        : "+f"(c[0]), "+f"(c[1]), "+f"(c[2]), "+f"(c[3])
        : "r"(a0), "r"(a1), "r"(a2), "r"(a3), "r"(b0), "r"(b1));
}

// ---------------- prep: L2-normalize rows -> fp16, word-permuted ----------------
__global__ void prep_kernel(const float* __restrict__ x) {
    __shared__ float sred[4];
    int row = blockIdx.x;
    int t = threadIdx.x;  // 128 threads
    float4 a = ((const float4*)(x + (size_t)row * D))[t];
    float ss = a.x * a.x + a.y * a.y + a.z * a.z + a.w * a.w;
    ss = warpReduceSum(ss);
    if ((t & 31) == 0) sred[t >> 5] = ss;
    __syncthreads();
    float tot = sred[0] + sred[1] + sred[2] + sred[3];
    float inv = 1.0f / fmaxf(sqrtf(tot), 1e-12f);
    float v[4] = {a.x * inv, a.y * inv, a.z * inv, a.w * inv};
    __half2* dst = (__half2*)(g_xnh + (size_t)row * D);
#pragma unroll
    for (int e = 0; e < 2; e++) {
        int w = 2 * t + e;  // logical word
        int wg = w & 7;
        int sp = (w & ~7) | (2 * (wg & 3) + (wg >> 2));
        dst[sp] = __floats2half2_rn(v[2 * e], v[2 * e + 1]);
    }
}

// ---------------- transpose x -> g_xth [512][8192] fp16, permuted k(columns) ----------------
__global__ void transpose_kernel(const float* __restrict__ x) {
    __shared__ float tl[32][33];
    int k0 = blockIdx.x * 32, n0 = blockIdx.y * 32;
    int tx = threadIdx.x, ty = threadIdx.y;  // 32 x 8
#pragma unroll
    for (int r = 0; r < 32; r += 8)
        tl[ty + r][tx] = x[(size_t)(k0 + ty + r) * D + n0 + tx];
    __syncthreads();
    // stored half position tx holds logical half lh
    int pw = (tx >> 1) & 7;
    int lh = (tx & ~15) | (2 * lword(pw) + (tx & 1));
#pragma unroll
    for (int r = 0; r < 32; r += 8)
        g_xth[(size_t)(n0 + ty + r) * NR + k0 + tx] = __float2half_rn(tl[lh][ty + r]);
}

// ============== GEMM1: E = exp(xn @ xn^T - 1) fp16, 128x256 tiles, mirror ==============
__global__ void __launch_bounds__(256, 1) gemm1_kernel() {
    // decode block: for each bj (0..31), bi in [0, min(64, 2bj+2))
    int kid = blockIdx.x, bj = 0;
    for (;;) {
        int cnum = min(64, 2 * bj + 2);
        if (kid < cnum) break;
        kid -= cnum; bj++;
    }
    int bi = kid;
    const int I0 = bi * 128, J0 = bj * 256;

    extern __shared__ uint32_t su[];
    uint32_t sbase = smem_u32(su);
    int t = threadIdx.x, wid = t >> 5, lane = t & 31;
    int g = lane >> 2, tq = lane & 3;
    int warpM = (wid >> 2) * 64, warpN = (wid & 3) * 64;

    const __half* aG = g_xnh + (size_t)(I0 + (t >> 1)) * D + (t & 1) * 32;
    const __half* bG = g_xnh + (size_t)(J0 + t) * D;
    uint32_t dstA = sbase + (uint32_t)((t >> 1) * ROWW + (t & 1) * 16) * 4;
    uint32_t dstB = sbase + (uint32_t)(A_TILE_W + t * ROWW) * 4;

    auto copy_stage = [&](int stage, int k0) {
        uint32_t off = (uint32_t)(stage * STAGE_W) * 4;
#pragma unroll
        for (int q = 0; q < 4; q++) cp16(dstA + off + q * 16, aG + k0 + q * 8);
#pragma unroll
        for (int q = 0; q < 8; q++) cp16(dstB + off + q * 16, bG + k0 + q * 8);
        CP_COMMIT();
    };

    float acc[4][8][4];
#pragma unroll
    for (int i = 0; i < 4; i++)
#pragma unroll
        for (int j = 0; j < 8; j++)
#pragma unroll
            for (int q = 0; q < 4; q++) acc[i][j][q] = 0.f;

    const int C = D / 64;  // 8 chunks
    copy_stage(0, 0);
    copy_stage(1, 64);
    CP_WAIT1();
    __syncthreads();

    for (int c = 0; c < C; c++) {
        const uint32_t* sA = su + (c & 1) * STAGE_W;
        const uint32_t* sB = sA + A_TILE_W;
#pragma unroll
        for (int s = 0; s < 4; s++) {  // 4 k16 steps per 64-half chunk
            uint32_t af[4][4], bf[8][2];
#pragma unroll
            for (int i = 0; i < 4; i++) {
                const uint32_t* pa = sA + (warpM + i * 16 + g) * ROWW + 8 * s + 2 * tq;
                uint2 lo = *(const uint2*)pa;              // (a0, a2)
                uint2 hi = *(const uint2*)(pa + 8 * ROWW); // (a1, a3)
                af[i][0] = lo.x; af[i][1] = hi.x; af[i][2] = lo.y; af[i][3] = hi.y;
            }
#pragma unroll
            for (int j = 0; j < 8; j++) {
                uint2 b = *(const uint2*)(sB + (warpN + j * 8 + g) * ROWW + 8 * s + 2 * tq);
                bf[j][0] = b.x; bf[j][1] = b.y;
            }
#pragma unroll
            for (int i = 0; i < 4; i++)
#pragma unroll
                for (int j = 0; j < 8; j++)
                    mma_f16(acc[i][j], af[i][0], af[i][1], af[i][2], af[i][3],
                            bf[j][0], bf[j][1]);
        }
        __syncthreads();
        if (c + 2 < C) { copy_stage(c & 1, (c + 2) * 64); CP_WAIT1(); }
        else CP_WAIT0();
        __syncthreads();
    }

    // ---- epilogue: exp(s-1) -> eb_w[128][131] half2 words -> permuted fp16 writes ----
    const int EBW = 131;  // word stride (odd-ish: 131 mod 32 = 3)
    uint32_t* eb = su;
#pragma unroll
    for (int i = 0; i < 4; i++)
#pragma unroll
        for (int j = 0; j < 8; j++) {
            int r0 = warpM + i * 16 + g;
            int wrd = ((warpN + j * 8) >> 1) + tq;
            __half2 lo = __floats2half2_rn(__expf(acc[i][j][0] - 1.0f), __expf(acc[i][j][1] - 1.0f));
            __half2 hi = __floats2half2_rn(__expf(acc[i][j][2] - 1.0f), __expf(acc[i][j][3] - 1.0f));
            eb[r0 * EBW + wrd]       = *(uint32_t*)&lo;
            eb[(r0 + 8) * EBW + wrd] = *(uint32_t*)&hi;
        }
    __syncthreads();

    // natural: rows I0+r, stored cols J0.. (perm): warp wid covers rows wid*16..+15
    {
        int b = 8 * (lane >> 1) + 2 * (lane & 1);
#pragma unroll 1
        for (int it = 0; it < 16; it++) {
            int r = wid * 16 + it;
            const uint32_t* src = eb + r * EBW;
            uint4 v = make_uint4(src[b], src[b + 4], src[b + 1], src[b + 5]);
            *(uint4*)(g_Eh + (size_t)(I0 + r) * NR + J0 + 8 * lane) = v;
        }
    }
    // mirror: rows J0+cc, stored cols I0.. (perm): warp covers rows wid*32..+31
    {
        int w = 8 * (lane >> 2) + (lane & 3);  // logical word for stored word pair 2lane
        int r0 = 2 * w;
#pragma unroll 1
        for (int it = 0; it < 32; it++) {
            int cc = wid * 32 + it;
            int cw = cc >> 1, ch = (cc & 1) * 16;
            uint32_t h0 = (eb[(r0)     * EBW + cw] >> ch) & 0xffffu;
            uint32_t h1 = (eb[(r0 + 1) * EBW + cw] >> ch) & 0xffffu;
            uint32_t h2 = (eb[(r0 + 8) * EBW + cw] >> ch) & 0xffffu;
            uint32_t h3 = (eb[(r0 + 9) * EBW + cw] >> ch) & 0xffffu;
            uint2 v = make_uint2(h0 | (h1 << 16), h2 | (h3 << 16));
            *(uint2*)(g_Eh + (size_t)(J0 + cc) * NR + I0 + 4 * lane) = v;
        }
    }
}

// ---------------- row sums of fp16 E -> invr ----------------
__global__ void rowsum_kernel() {
    __shared__ float sred[8];
    int row = blockIdx.x, t = threadIdx.x;  // 256 threads
    const uint4* e = (const uint4*)(g_Eh + (size_t)row * NR);  // 1024 uint4/row
    float s = 0.f;
#pragma unroll
    for (int i = 0; i < 4; i++) {
        uint4 v = e[t + 256 * i];
        const __half2* hp = (const __half2*)&v;
#pragma unroll
        for (int k = 0; k < 4; k++) {
            float2 f = __half22float2(hp[k]);
            s += f.x + f.y;
        }
    }
    s = warpReduceSum(s);
    if ((t & 31) == 0) sred[t >> 5] = s;
    __syncthreads();
    if (t == 0) {
        float tot = 0.f;
#pragma unroll
        for (int i = 0; i < 8; i++) tot += sred[i];
        g_invr[row] = 1.0f / tot;
    }
}

__global__ void permute_invr_kernel() {
    int sp = blockIdx.x * 256 + threadIdx.x;
    int pw = (sp >> 1) & 7;
    int logical = (sp & ~15) | (2 * lword(pw) + (sp & 1));
    g_invr_p[sp] = g_invr[logical];
}

// ============== GEMM2: xneg = [E*(invr_i+invr_k)] @ x, 128x256 tiles ==============
__global__ void __launch_bounds__(256, 1) gemm2_kernel() {
    const int n0 = blockIdx.x * 256;  // 0..1
    const int I0 = blockIdx.y * 128;  // 0..63

    extern __shared__ uint32_t su[];
    uint32_t sbase = smem_u32(su);
    int t = threadIdx.x, wid = t >> 5, lane = t & 31;
    int g = lane >> 2, tq = lane & 3;
    int warpM = (wid >> 2) * 64, warpN = (wid & 3) * 64;

    const float ri = g_invr[I0 + (t >> 1)];
    const __half* aG = g_Eh + (size_t)(I0 + (t >> 1)) * NR + (t & 1) * 32;  // stored-perm rows
    const __half* bG = g_xth + (size_t)(n0 + t) * NR;                       // stored-perm rows
    uint32_t stsA = sbase + (uint32_t)((t >> 1) * ROWW + (t & 1) * 16) * 4;
    uint32_t dstB = sbase + (uint32_t)(A_TILE_W + t * ROWW) * 4;

    uint4 pa[4];
    auto ldgA = [&](int k0) {
#pragma unroll
        for (int q = 0; q < 4; q++) pa[q] = ((const uint4*)(aG + k0))[q];
    };
    auto stsA_f = [&](int stage, int k0) {
        const float* rp = g_invr_p + k0 + (t & 1) * 32;
        uint32_t dst = stsA + (uint32_t)(stage * STAGE_W) * 4;
#pragma unroll
        for (int q = 0; q < 4; q++) {
            float4 r0 = __ldg((const float4*)(rp + q * 8));
            float4 r1 = __ldg((const float4*)(rp + q * 8 + 4));
            const __half2* hp = (const __half2*)&pa[q];
            float2 f0 = __half22float2(hp[0]);
            float2 f1 = __half22float2(hp[1]);
            float2 f2 = __half22float2(hp[2]);
            float2 f3 = __half22float2(hp[3]);
            __half2 o0 = __floats2half2_rn(f0.x * (ri + r0.x), f0.y * (ri + r0.y));
            __half2 o1 = __floats2half2_rn(f1.x * (ri + r0.z), f1.y * (ri + r0.w));
            __half2 o2 = __floats2half2_rn(f2.x * (ri + r1.x), f2.y * (ri + r1.y));
            __half2 o3 = __floats2half2_rn(f3.x * (ri + r1.z), f3.y * (ri + r1.w));
            asm volatile("st.shared.v4.b32 [%0], {%1,%2,%3,%4};"
                         :: "r"(dst + q * 16), "r"(*(uint32_t*)&o0), "r"(*(uint32_t*)&o1),
                            "r"(*(uint32_t*)&o2), "r"(*(uint32_t*)&o3));
        }
    };
    auto cpB = [&](int stage, int k0) {
        uint32_t off = (uint32_t)(stage * STAGE_W) * 4;
#pragma unroll
        for (int q = 0; q < 8; q++) cp16(dstB + off + q * 16, bG + k0 + q * 8);
        CP_COMMIT();
    };

    float acc[4][8][4];
#pragma unroll
    for (int i = 0; i < 4; i++)
#pragma unroll
        for (int j = 0; j < 8; j++)
#pragma unroll
            for (int q = 0; q < 4; q++) acc[i][j][q] = 0.f;

    const int C = NR / 64;  // 128 chunks
    ldgA(0); stsA_f(0, 0); cpB(0, 0);
    ldgA(64);
    cpB(1, 64);
    CP_WAIT1();
    __syncthreads();

    for (int c = 0; c < C; c++) {
        if (c + 1 < C) stsA_f((c + 1) & 1, (c + 1) * 64);
        if (c + 2 < C) ldgA((c + 2) * 64);
        const uint32_t* sA = su + (c & 1) * STAGE_W;
        const uint32_t* sB = sA + A_TILE_W;
#pragma unroll
        for (int s = 0; s < 4; s++) {
            uint32_t af[4][4], bf[8][2];
#pragma unroll
            for (int i = 0; i < 4; i++) {
                const uint32_t* p = sA + (warpM + i * 16 + g) * ROWW + 8 * s + 2 * tq;
                uint2 lo = *(const uint2*)p;
                uint2 hi = *(const uint2*)(p + 8 * ROWW);
                af[i][0] = lo.x; af[i][1] = hi.x; af[i][2] = lo.y; af[i][3] = hi.y;
            }
#pragma unroll
            for (int j = 0; j < 8; j++) {
                uint2 b = *(const uint2*)(sB + (warpN + j * 8 + g) * ROWW + 8 * s + 2 * tq);
                bf[j][0] = b.x; bf[j][1] = b.y;
            }
#pragma unroll
            for (int i = 0; i < 4; i++)
#pragma unroll
                for (int j = 0; j < 8; j++)
                    mma_f16(acc[i][j], af[i][0], af[i][1], af[i][2], af[i][3],
                            bf[j][0], bf[j][1]);
        }
        __syncthreads();
        if (c + 2 < C) { cpB(c & 1, (c + 2) * 64); CP_WAIT1(); }
        else CP_WAIT0();
        __syncthreads();
    }

    // epilogue: f32 stores, n not permuted
#pragma unroll
    for (int i = 0; i < 4; i++)
#pragma unroll
        for (int j = 0; j < 8; j++) {
            int r0 = I0 + warpM + i * 16 + g;
            int c0 = n0 + warpN + j * 8 + 2 * tq;
            *(float2*)(g_xneg + (size_t)r0 * D + c0)       = make_float2(acc[i][j][0], acc[i][j][1]);
            *(float2*)(g_xneg + (size_t)(r0 + 8) * D + c0) = make_float2(acc[i][j][2], acc[i][j][3]);
        }
}

// ---------------- y = x - SCALE*xneg, LayerNorm ----------------
__global__ void ln_kernel(const float* __restrict__ x, const float* __restrict__ gamma,
                          const float* __restrict__ beta, float* __restrict__ out) {
    __shared__ float s1[4], s2[4];
    int row = blockIdx.x, t = threadIdx.x;  // 128 threads
    float4 xv = ((const float4*)(x + (size_t)row * D))[t];
    float4 nv = ((const float4*)(g_xneg + (size_t)row * D))[t];
    float4 y = make_float4(xv.x - SCALEF * nv.x, xv.y - SCALEF * nv.y,
                           xv.z - SCALEF * nv.z, xv.w - SCALEF * nv.w);
    float s = y.x + y.y + y.z + y.w;
    float q = y.x * y.x + y.y * y.y + y.z * y.z + y.w * y.w;
    s = warpReduceSum(s);
    q = warpReduceSum(q);
    if ((t & 31) == 0) { s1[t >> 5] = s; s2[t >> 5] = q; }
    __syncthreads();
    float sum = s1[0] + s1[1] + s1[2] + s1[3];
    float sq  = s2[0] + s2[1] + s2[2] + s2[3];
    float mean = sum * (1.0f / D);
    float var = sq * (1.0f / D) - mean * mean;
    float rstd = rsqrtf(var + 1e-6f);
    float4 gm = ((const float4*)gamma)[t];
    float4 b = ((const float4*)beta)[t];
    float4 o;
    o.x = (y.x - mean) * rstd * gm.x + b.x;
    o.y = (y.y - mean) * rstd * gm.y + b.y;
    o.z = (y.z - mean) * rstd * gm.z + b.z;
    o.w = (y.w - mean) * rstd * gm.w + b.w;
    ((float4*)out)[(size_t)row * (D / 4) + t] = o;
}

extern "C" void kernel_launch(void* const* d_in, const int* in_sizes, int n_in,
                              void* d_out, int out_size) {
    const float* x     = (const float*)d_in[0];
    const float* gamma = (const float*)d_in[1];
    const float* beta  = (const float*)d_in[2];
    float* out = (float*)d_out;

    cudaFuncSetAttribute(gemm1_kernel, cudaFuncAttributeMaxDynamicSharedMemorySize, SMEM_BYTES);
    cudaFuncSetAttribute(gemm2_kernel, cudaFuncAttributeMaxDynamicSharedMemorySize, SMEM_BYTES);

    prep_kernel<<<NR, 128>>>(x);
    transpose_kernel<<<dim3(NR / 32, D / 32), dim3(32, 8)>>>(x);
    gemm1_kernel<<<1056, 256, SMEM_BYTES>>>();
    rowsum_kernel<<<NR, 256>>>();
    permute_invr_kernel<<<NR / 256, 256>>>();
    gemm2_kernel<<<dim3(2, 64), 256, SMEM_BYTES>>>();
    ln_kernel<<<NR, 128>>>(x, gamma, beta, out);
}

// round 7
// speedup vs baseline: 2.3190x; 1.0613x over previous
#include <cuda_runtime.h>
#include <cuda_fp16.h>
#include <math.h>
#include <stdint.h>

#define NR 8192
#define D  512
#define SCALEF 0.1f

__device__ __half g_Eh[(size_t)NR * NR];     // 128 MB: E fp16, k-word-permuted columns
__device__ __half g_xnh[(size_t)NR * D];     // normalized x fp16, permuted features
__device__ __half g_xth[(size_t)D * NR];     // x^T fp16 [512][8192], permuted columns
__device__ float  g_xneg[(size_t)NR * D];
__device__ float  g_invr[NR];                // natural order
__device__ float  g_invr_p[NR];              // stored(half)-position order

// word-level perm within 8-word (16-half) groups: stored word p holds logical word
// l(p) = (p>>1) + 4*(p&1); inverse: logical w stored at 2*(w&3) + (w>>2)
__device__ __host__ __forceinline__ int lword(int p) { return (p >> 1) + 4 * (p & 1); }

#define ROWW 40                   // smem row stride in 32-bit words (rows hold 32 data words)
#define A_TILE_W (128 * ROWW)     // 5120
#define B_TILE_W (256 * ROWW)     // 10240
#define STAGE_W  (A_TILE_W + B_TILE_W)     // 15360 words
#define NSTAGE 3
#define SMEM_BYTES (NSTAGE * STAGE_W * 4)  // 184320

__device__ __forceinline__ float warpReduceSum(float v) {
#pragma unroll
    for (int o = 16; o > 0; o >>= 1) v += __shfl_xor_sync(0xffffffffu, v, o);
    return v;
}
__device__ __forceinline__ uint32_t smem_u32(const void* p) {
    uint32_t a;
    asm("{ .reg .u64 t; cvta.to.shared.u64 t, %1; cvt.u32.u64 %0, t; }" : "=r"(a) : "l"(p));
    return a;
}
__device__ __forceinline__ void cp16(uint32_t s, const void* g) {
    asm volatile("cp.async.cg.shared.global [%0], [%1], 16;" :: "r"(s), "l"(g));
}
#define CP_COMMIT() asm volatile("cp.async.commit_group;")
#define CP_WAIT1()  asm volatile("cp.async.wait_group 1;")
#define CP_WAIT0()  asm volatile("cp.async.wait_group 0;")

__device__ __forceinline__ void mma_f16(float* c, uint32_t a0, uint32_t a1, uint32_t a2,
                                        uint32_t a3, uint32_t b0, uint32_t b1) {
    asm volatile(
        "mma.sync.aligned.m16n8k16.row.col.f32.f16.f16.f32 "
        "{%0,%1,%2,%3}, {%4,%5,%6,%7}, {%8,%9}, {%0,%1,%2,%3};"
        : "+f"(c[0]), "+f"(c[1]), "+f"(c[2]), "+f"(c[3])
        : "r"(a0), "r"(a1), "r"(a2), "r"(a3), "r"(b0), "r"(b1));
}

// ---------------- prep: L2-normalize rows -> fp16, word-permuted ----------------
__global__ void prep_kernel(const float* __restrict__ x) {
    __shared__ float sred[4];
    int row = blockIdx.x;
    int t = threadIdx.x;  // 128 threads
    float4 a = ((const float4*)(x + (size_t)row * D))[t];
    float ss = a.x * a.x + a.y * a.y + a.z * a.z + a.w * a.w;
    ss = warpReduceSum(ss);
    if ((t & 31) == 0) sred[t >> 5] = ss;
    __syncthreads();
    float tot = sred[0] + sred[1] + sred[2] + sred[3];
    float inv = 1.0f / fmaxf(sqrtf(tot), 1e-12f);
    float v[4] = {a.x * inv, a.y * inv, a.z * inv, a.w * inv};
    __half2* dst = (__half2*)(g_xnh + (size_t)row * D);
#pragma unroll
    for (int e = 0; e < 2; e++) {
        int w = 2 * t + e;  // logical word
        int wg = w & 7;
        int sp = (w & ~7) | (2 * (wg & 3) + (wg >> 2));
        dst[sp] = __floats2half2_rn(v[2 * e], v[2 * e + 1]);
    }
}

// ---------------- transpose x -> g_xth [512][8192] fp16, permuted k(columns) ----------------
__global__ void transpose_kernel(const float* __restrict__ x) {
    __shared__ float tl[32][33];
    int k0 = blockIdx.x * 32, n0 = blockIdx.y * 32;
    int tx = threadIdx.x, ty = threadIdx.y;  // 32 x 8
#pragma unroll
    for (int r = 0; r < 32; r += 8)
        tl[ty + r][tx] = x[(size_t)(k0 + ty + r) * D + n0 + tx];
    __syncthreads();
    int pw = (tx >> 1) & 7;
    int lh = (tx & ~15) | (2 * lword(pw) + (tx & 1));
#pragma unroll
    for (int r = 0; r < 32; r += 8)
        g_xth[(size_t)(n0 + ty + r) * NR + k0 + tx] = __float2half_rn(tl[lh][ty + r]);
}

// ============== GEMM1: E = exp(xn @ xn^T - 1) fp16, 128x256 tiles, mirror ==============
__global__ void __launch_bounds__(256, 1) gemm1_kernel() {
    // decode block: for each bj (0..31), bi in [0, min(64, 2bj+2))
    int kid = blockIdx.x, bj = 0;
    for (;;) {
        int cnum = min(64, 2 * bj + 2);
        if (kid < cnum) break;
        kid -= cnum; bj++;
    }
    int bi = kid;
    const int I0 = bi * 128, J0 = bj * 256;

    extern __shared__ uint32_t su[];
    uint32_t sbase = smem_u32(su);
    int t = threadIdx.x, wid = t >> 5, lane = t & 31;
    int g = lane >> 2, tq = lane & 3;
    int warpM = (wid >> 2) * 64, warpN = (wid & 3) * 64;

    const __half* aG = g_xnh + (size_t)(I0 + (t >> 1)) * D + (t & 1) * 32;
    const __half* bG = g_xnh + (size_t)(J0 + t) * D;
    uint32_t dstA = sbase + (uint32_t)((t >> 1) * ROWW + (t & 1) * 16) * 4;
    uint32_t dstB = sbase + (uint32_t)(A_TILE_W + t * ROWW) * 4;

    auto copy_stage = [&](int stage, int k0) {
        uint32_t off = (uint32_t)(stage * STAGE_W) * 4;
#pragma unroll
        for (int q = 0; q < 4; q++) cp16(dstA + off + q * 16, aG + k0 + q * 8);
#pragma unroll
        for (int q = 0; q < 8; q++) cp16(dstB + off + q * 16, bG + k0 + q * 8);
        CP_COMMIT();
    };

    float acc[4][8][4];
#pragma unroll
    for (int i = 0; i < 4; i++)
#pragma unroll
        for (int j = 0; j < 8; j++)
#pragma unroll
            for (int q = 0; q < 4; q++) acc[i][j][q] = 0.f;

    const int C = D / 64;  // 8 chunks
    copy_stage(0, 0);
    copy_stage(1, 64);

    int stage = 0;
    for (int c = 0; c < C; c++) {
        if (c + 2 < C) CP_WAIT1(); else CP_WAIT0();
        __syncthreads();
        if (c + 2 < C) {
            int ns = stage + 2; if (ns >= NSTAGE) ns -= NSTAGE;
            copy_stage(ns, (c + 2) * 64);
        }
        const uint32_t* sA = su + stage * STAGE_W;
        const uint32_t* sB = sA + A_TILE_W;
#pragma unroll
        for (int s = 0; s < 4; s++) {  // 4 k16 steps per 64-half chunk
            uint32_t af[4][4], bf[8][2];
#pragma unroll
            for (int i = 0; i < 4; i++) {
                const uint32_t* pa = sA + (warpM + i * 16 + g) * ROWW + 8 * s + 2 * tq;
                uint2 lo = *(const uint2*)pa;              // (a0, a2)
                uint2 hi = *(const uint2*)(pa + 8 * ROWW); // (a1, a3)
                af[i][0] = lo.x; af[i][1] = hi.x; af[i][2] = lo.y; af[i][3] = hi.y;
            }
#pragma unroll
            for (int j = 0; j < 8; j++) {
                uint2 b = *(const uint2*)(sB + (warpN + j * 8 + g) * ROWW + 8 * s + 2 * tq);
                bf[j][0] = b.x; bf[j][1] = b.y;
            }
#pragma unroll
            for (int i = 0; i < 4; i++)
#pragma unroll
                for (int j = 0; j < 8; j++)
                    mma_f16(acc[i][j], af[i][0], af[i][1], af[i][2], af[i][3],
                            bf[j][0], bf[j][1]);
        }
        if (++stage >= NSTAGE) stage = 0;
    }
    __syncthreads();

    // ---- epilogue: exp(s-1) -> eb_w[128][131] half2 words -> permuted fp16 writes ----
    const int EBW = 131;
    uint32_t* eb = su;
#pragma unroll
    for (int i = 0; i < 4; i++)
#pragma unroll
        for (int j = 0; j < 8; j++) {
            int r0 = warpM + i * 16 + g;
            int wrd = ((warpN + j * 8) >> 1) + tq;
            __half2 lo = __floats2half2_rn(__expf(acc[i][j][0] - 1.0f), __expf(acc[i][j][1] - 1.0f));
            __half2 hi = __floats2half2_rn(__expf(acc[i][j][2] - 1.0f), __expf(acc[i][j][3] - 1.0f));
            eb[r0 * EBW + wrd]       = *(uint32_t*)&lo;
            eb[(r0 + 8) * EBW + wrd] = *(uint32_t*)&hi;
        }
    __syncthreads();

    // natural: rows I0+r, stored cols J0..: warp wid covers rows wid*16..+15
    {
        int b = 8 * (lane >> 1) + 2 * (lane & 1);
#pragma unroll 1
        for (int it = 0; it < 16; it++) {
            int r = wid * 16 + it;
            const uint32_t* src = eb + r * EBW;
            uint4 v = make_uint4(src[b], src[b + 4], src[b + 1], src[b + 5]);
            *(uint4*)(g_Eh + (size_t)(I0 + r) * NR + J0 + 8 * lane) = v;
        }
    }
    // mirror: rows J0+cc, stored cols I0..: warp covers rows wid*32..+31
    {
        int w = 8 * (lane >> 2) + (lane & 3);
        int r0 = 2 * w;
#pragma unroll 1
        for (int it = 0; it < 32; it++) {
            int cc = wid * 32 + it;
            int cw = cc >> 1, ch = (cc & 1) * 16;
            uint32_t h0 = (eb[(r0)     * EBW + cw] >> ch) & 0xffffu;
            uint32_t h1 = (eb[(r0 + 1) * EBW + cw] >> ch) & 0xffffu;
            uint32_t h2 = (eb[(r0 + 8) * EBW + cw] >> ch) & 0xffffu;
            uint32_t h3 = (eb[(r0 + 9) * EBW + cw] >> ch) & 0xffffu;
            uint2 v = make_uint2(h0 | (h1 << 16), h2 | (h3 << 16));
            *(uint2*)(g_Eh + (size_t)(J0 + cc) * NR + I0 + 4 * lane) = v;
        }
    }
}

// ---------------- row sums of fp16 E -> invr ----------------
__global__ void rowsum_kernel() {
    __shared__ float sred[8];
    int row = blockIdx.x, t = threadIdx.x;  // 256 threads
    const uint4* e = (const uint4*)(g_Eh + (size_t)row * NR);
    float s = 0.f;
#pragma unroll
    for (int i = 0; i < 4; i++) {
        uint4 v = e[t + 256 * i];
        const __half2* hp = (const __half2*)&v;
#pragma unroll
        for (int k = 0; k < 4; k++) {
            float2 f = __half22float2(hp[k]);
            s += f.x + f.y;
        }
    }
    s = warpReduceSum(s);
    if ((t & 31) == 0) sred[t >> 5] = s;
    __syncthreads();
    if (t == 0) {
        float tot = 0.f;
#pragma unroll
        for (int i = 0; i < 8; i++) tot += sred[i];
        g_invr[row] = 1.0f / tot;
    }
}

__global__ void permute_invr_kernel() {
    int sp = blockIdx.x * 256 + threadIdx.x;
    int pw = (sp >> 1) & 7;
    int logical = (sp & ~15) | (2 * lword(pw) + (sp & 1));
    g_invr_p[sp] = g_invr[logical];
}

// ============== GEMM2: xneg = [E*(invr_i+invr_k)] @ x, 128x256 tiles ==============
__global__ void __launch_bounds__(256, 1) gemm2_kernel() {
    const int n0 = blockIdx.x * 256;  // 0..1
    const int I0 = blockIdx.y * 128;  // 0..63

    extern __shared__ uint32_t su[];
    uint32_t sbase = smem_u32(su);
    int t = threadIdx.x, wid = t >> 5, lane = t & 31;
    int g = lane >> 2, tq = lane & 3;
    int warpM = (wid >> 2) * 64, warpN = (wid & 3) * 64;

    const float ri = g_invr[I0 + (t >> 1)];
    const __half* aG = g_Eh + (size_t)(I0 + (t >> 1)) * NR + (t & 1) * 32;
    const __half* bG = g_xth + (size_t)(n0 + t) * NR;
    uint32_t stsA = sbase + (uint32_t)((t >> 1) * ROWW + (t & 1) * 16) * 4;
    uint32_t dstB = sbase + (uint32_t)(A_TILE_W + t * ROWW) * 4;

    uint4 pa[4];
    auto ldgA = [&](int k0) {
#pragma unroll
        for (int q = 0; q < 4; q++) pa[q] = ((const uint4*)(aG + k0))[q];
    };
    auto stsA_f = [&](int stg, int k0) {
        const float* rp = g_invr_p + k0 + (t & 1) * 32;
        uint32_t dst = stsA + (uint32_t)(stg * STAGE_W) * 4;
#pragma unroll
        for (int q = 0; q < 4; q++) {
            float4 r0 = __ldg((const float4*)(rp + q * 8));
            float4 r1 = __ldg((const float4*)(rp + q * 8 + 4));
            const __half2* hp = (const __half2*)&pa[q];
            float2 f0 = __half22float2(hp[0]);
            float2 f1 = __half22float2(hp[1]);
            float2 f2 = __half22float2(hp[2]);
            float2 f3 = __half22float2(hp[3]);
            __half2 o0 = __floats2half2_rn(f0.x * (ri + r0.x), f0.y * (ri + r0.y));
            __half2 o1 = __floats2half2_rn(f1.x * (ri + r0.z), f1.y * (ri + r0.w));
            __half2 o2 = __floats2half2_rn(f2.x * (ri + r1.x), f2.y * (ri + r1.y));
            __half2 o3 = __floats2half2_rn(f3.x * (ri + r1.z), f3.y * (ri + r1.w));
            asm volatile("st.shared.v4.b32 [%0], {%1,%2,%3,%4};"
                         :: "r"(dst + q * 16), "r"(*(uint32_t*)&o0), "r"(*(uint32_t*)&o1),
                            "r"(*(uint32_t*)&o2), "r"(*(uint32_t*)&o3));
        }
    };
    auto cpB = [&](int stg, int k0) {
        uint32_t off = (uint32_t)(stg * STAGE_W) * 4;
#pragma unroll
        for (int q = 0; q < 8; q++) cp16(dstB + off + q * 16, bG + k0 + q * 8);
        CP_COMMIT();
    };

    float acc[4][8][4];
#pragma unroll
    for (int i = 0; i < 4; i++)
#pragma unroll
        for (int j = 0; j < 8; j++)
#pragma unroll
            for (int q = 0; q < 4; q++) acc[i][j][q] = 0.f;

    const int C = NR / 64;  // 128 chunks
    ldgA(0); stsA_f(0, 0); cpB(0, 0);
    ldgA(64); stsA_f(1, 64); cpB(1, 64);
    ldgA(128);

    int stage = 0;
    for (int c = 0; c < C; c++) {
        if (c + 2 < C) CP_WAIT1(); else CP_WAIT0();
        __syncthreads();
        if (c + 2 < C) {
            int ns = stage + 2; if (ns >= NSTAGE) ns -= NSTAGE;
            stsA_f(ns, (c + 2) * 64);   // consumes pa (chunk c+2)
            cpB(ns, (c + 2) * 64);
            if (c + 3 < C) ldgA((c + 3) * 64);
        }
        const uint32_t* sA = su + stage * STAGE_W;
        const uint32_t* sB = sA + A_TILE_W;
#pragma unroll
        for (int s = 0; s < 4; s++) {
            uint32_t af[4][4], bf[8][2];
#pragma unroll
            for (int i = 0; i < 4; i++) {
                const uint32_t* p = sA + (warpM + i * 16 + g) * ROWW + 8 * s + 2 * tq;
                uint2 lo = *(const uint2*)p;
                uint2 hi = *(const uint2*)(p + 8 * ROWW);
                af[i][0] = lo.x; af[i][1] = hi.x; af[i][2] = lo.y; af[i][3] = hi.y;
            }
#pragma unroll
            for (int j = 0; j < 8; j++) {
                uint2 b = *(const uint2*)(sB + (warpN + j * 8 + g) * ROWW + 8 * s + 2 * tq);
                bf[j][0] = b.x; bf[j][1] = b.y;
            }
#pragma unroll
            for (int i = 0; i < 4; i++)
#pragma unroll
                for (int j = 0; j < 8; j++)
                    mma_f16(acc[i][j], af[i][0], af[i][1], af[i][2], af[i][3],
                            bf[j][0], bf[j][1]);
        }
        if (++stage >= NSTAGE) stage = 0;
    }

    // epilogue: f32 stores, n not permuted
#pragma unroll
    for (int i = 0; i < 4; i++)
#pragma unroll
        for (int j = 0; j < 8; j++) {
            int r0 = I0 + warpM + i * 16 + g;
            int c0 = n0 + warpN + j * 8 + 2 * tq;
            *(float2*)(g_xneg + (size_t)r0 * D + c0)       = make_float2(acc[i][j][0], acc[i][j][1]);
            *(float2*)(g_xneg + (size_t)(r0 + 8) * D + c0) = make_float2(acc[i][j][2], acc[i][j][3]);
        }
}

// ---------------- y = x - SCALE*xneg, LayerNorm ----------------
__global__ void ln_kernel(const float* __restrict__ x, const float* __restrict__ gamma,
                          const float* __restrict__ beta, float* __restrict__ out) {
    __shared__ float s1[4], s2[4];
    int row = blockIdx.x, t = threadIdx.x;  // 128 threads
    float4 xv = ((const float4*)(x + (size_t)row * D))[t];
    float4 nv = ((const float4*)(g_xneg + (size_t)row * D))[t];
    float4 y = make_float4(xv.x - SCALEF * nv.x, xv.y - SCALEF * nv.y,
                           xv.z - SCALEF * nv.z, xv.w - SCALEF * nv.w);
    float s = y.x + y.y + y.z + y.w;
    float q = y.x * y.x + y.y * y.y + y.z * y.z + y.w * y.w;
    s = warpReduceSum(s);
    q = warpReduceSum(q);
    if ((t & 31) == 0) { s1[t >> 5] = s; s2[t >> 5] = q; }
    __syncthreads();
    float sum = s1[0] + s1[1] + s1[2] + s1[3];
    float sq  = s2[0] + s2[1] + s2[2] + s2[3];
    float mean = sum * (1.0f / D);
    float var = sq * (1.0f / D) - mean * mean;
    float rstd = rsqrtf(var + 1e-6f);
    float4 gm = ((const float4*)gamma)[t];
    float4 b = ((const float4*)beta)[t];
    float4 o;
    o.x = (y.x - mean) * rstd * gm.x + b.x;
    o.y = (y.y - mean) * rstd * gm.y + b.y;
    o.z = (y.z - mean) * rstd * gm.z + b.z;
    o.w = (y.w - mean) * rstd * gm.w + b.w;
    ((float4*)out)[(size_t)row * (D / 4) + t] = o;
}

extern "C" void kernel_launch(void* const* d_in, const int* in_sizes, int n_in,
                              void* d_out, int out_size) {
    const float* x     = (const float*)d_in[0];
    const float* gamma = (const float*)d_in[1];
    const float* beta  = (const float*)d_in[2];
    float* out = (float*)d_out;

    cudaFuncSetAttribute(gemm1_kernel, cudaFuncAttributeMaxDynamicSharedMemorySize, SMEM_BYTES);
    cudaFuncSetAttribute(gemm2_kernel, cudaFuncAttributeMaxDynamicSharedMemorySize, SMEM_BYTES);

    prep_kernel<<<NR, 128>>>(x);
    transpose_kernel<<<dim3(NR / 32, D / 32), dim3(32, 8)>>>(x);
    gemm1_kernel<<<1056, 256, SMEM_BYTES>>>();
    rowsum_kernel<<<NR, 256>>>();
    permute_invr_kernel<<<NR / 256, 256>>>();
    gemm2_kernel<<<dim3(2, 64), 256, SMEM_BYTES>>>();
    ln_kernel<<<NR, 128>>>(x, gamma, beta, out);
}